// round 14
// baseline (speedup 1.0000x reference)
#include <cuda_runtime.h>
#include <cuda_bf16.h>
#include <math.h>
#include <cstdint>

// NT-Xent loss, N=4096, D=256, T=0.5, EPS=1e-8.
// loss = (S_d - 2N*S_p) / (2N)^2
//   S_p = (2/T) * sum_i dot(z_i, z_j)/(|z_i||z_j|)   (fp32, from raw inputs)
//   S_d = sum_j [(2N-1)*log(rs_j) + log(max(rs_j-1,EPS))]
//   rs_j = sum_k exp(sim_jk/T); sim = zn@zn^T        (bf16 HMMA, symmetric:
//   lower-triangle tiles only; off-diag tiles emit row AND col sums)
// R14: k_simexp at 512 threads / 16 warps (4x4), warp tile 32x32, 32 accs/thr,
// __launch_bounds__(512,2) -> 2 CTAs/SM = 32 warps/SM (was RF-capped at 16).

#define NROWS 8192
#define NHALF 4096
#define DDIM  256
#define LOG2E_X2 2.8853900817779268f   // exp(2s) = 2^(s*2*log2 e)

__device__ __nv_bfloat16 g_znb[NROWS * DDIM];   // bf16 normalized
__device__ float         g_rs [NROWS];
__device__ float         g_sum_p;
__device__ double        g_sd;
__device__ int           g_ticket;

// ===================== PTX helpers ==========================================
__device__ __forceinline__ uint32_t smem_u32(const void* p) {
    uint32_t a;
    asm("{ .reg .u64 t; cvta.to.shared.u64 t, %1; cvt.u32.u64 %0, t; }" : "=r"(a) : "l"(p));
    return a;
}
#define CP_ASYNC16(sm, gp) \
    asm volatile("cp.async.cg.shared.global [%0], [%1], 16;" :: "r"(sm), "l"(gp))
#define CP_COMMIT() asm volatile("cp.async.commit_group;" ::: "memory")
#define CP_WAIT_1() asm volatile("cp.async.wait_group 1;" ::: "memory")
#define CP_WAIT_0() asm volatile("cp.async.wait_group 0;" ::: "memory")

#define LDSM_X4(r0, r1, r2, r3, addr) \
    asm volatile("ldmatrix.sync.aligned.m8n8.x4.shared.b16 {%0,%1,%2,%3}, [%4];" \
        : "=r"(r0), "=r"(r1), "=r"(r2), "=r"(r3) : "r"(addr))

#define MMA16816(d, a, b0, b1) \
    asm volatile("mma.sync.aligned.m16n8k16.row.col.f32.bf16.bf16.f32 " \
        "{%0,%1,%2,%3}, {%4,%5,%6,%7}, {%8,%9}, {%0,%1,%2,%3};" \
        : "+f"((d)[0]), "+f"((d)[1]), "+f"((d)[2]), "+f"((d)[3]) \
        : "r"((a)[0]), "r"((a)[1]), "r"((a)[2]), "r"((a)[3]), "r"(b0), "r"(b1))

__device__ __forceinline__ float ex2f(float x) {
    float y; asm("ex2.approx.f32 %0, %1;" : "=f"(y) : "f"(x)); return y;
}

// ===================== Kernel 1: prep = normalize + positives ===============
// One warp per TWO pairs (MLP 8); writes bf16 zn rows; accumulates S_p.
__global__ void __launch_bounds__(256) k_prep(const float* __restrict__ zi,
                                              const float* __restrict__ zj) {
    int gtid = blockIdx.x * 256 + threadIdx.x;
    if (gtid < NROWS) g_rs[gtid] = 0.0f;
    if (gtid == 0) { g_sum_p = 0.0f; g_sd = 0.0; g_ticket = 0; }

    int warp = gtid >> 5;          // 0..2047
    int lane = threadIdx.x & 31;
    int p0   = warp * 2;
    if (p0 >= NHALF) return;

    const float4* a0p = (const float4*)(zi + (size_t)p0 * DDIM);
    const float4* b0p = (const float4*)(zj + (size_t)p0 * DDIM);
    const float4* a1p = (const float4*)(zi + (size_t)(p0 + 1) * DDIM);
    const float4* b1p = (const float4*)(zj + (size_t)(p0 + 1) * DDIM);
    float4 A0 = a0p[lane], A1 = a0p[lane + 32];
    float4 B0 = b0p[lane], B1 = b0p[lane + 32];
    float4 C0 = a1p[lane], C1 = a1p[lane + 32];
    float4 D0 = b1p[lane], D1 = b1p[lane + 32];

    float si0 = A0.x*A0.x+A0.y*A0.y+A0.z*A0.z+A0.w*A0.w + A1.x*A1.x+A1.y*A1.y+A1.z*A1.z+A1.w*A1.w;
    float sj0 = B0.x*B0.x+B0.y*B0.y+B0.z*B0.z+B0.w*B0.w + B1.x*B1.x+B1.y*B1.y+B1.z*B1.z+B1.w*B1.w;
    float dd0 = A0.x*B0.x+A0.y*B0.y+A0.z*B0.z+A0.w*B0.w + A1.x*B1.x+A1.y*B1.y+A1.z*B1.z+A1.w*B1.w;
    float si1 = C0.x*C0.x+C0.y*C0.y+C0.z*C0.z+C0.w*C0.w + C1.x*C1.x+C1.y*C1.y+C1.z*C1.z+C1.w*C1.w;
    float sj1 = D0.x*D0.x+D0.y*D0.y+D0.z*D0.z+D0.w*D0.w + D1.x*D1.x+D1.y*D1.y+D1.z*D1.z+D1.w*D1.w;
    float dd1 = C0.x*D0.x+C0.y*D0.y+C0.z*D0.z+C0.w*D0.w + C1.x*D1.x+C1.y*D1.y+C1.z*D1.z+C1.w*D1.w;
    #pragma unroll
    for (int o = 16; o > 0; o >>= 1) {
        si0 += __shfl_xor_sync(0xffffffffu, si0, o);
        sj0 += __shfl_xor_sync(0xffffffffu, sj0, o);
        dd0 += __shfl_xor_sync(0xffffffffu, dd0, o);
        si1 += __shfl_xor_sync(0xffffffffu, si1, o);
        sj1 += __shfl_xor_sync(0xffffffffu, sj1, o);
        dd1 += __shfl_xor_sync(0xffffffffu, dd1, o);
    }
    float ii0 = 1.0f / fmaxf(sqrtf(si0), 1e-8f);
    float ij0 = 1.0f / fmaxf(sqrtf(sj0), 1e-8f);
    float ii1 = 1.0f / fmaxf(sqrtf(si1), 1e-8f);
    float ij1 = 1.0f / fmaxf(sqrtf(sj1), 1e-8f);

    if (lane == 0)
        atomicAdd(&g_sum_p, 4.0f * (dd0 * ii0 * ij0 + dd1 * ii1 * ij1)); // 2/T = 4

    __nv_bfloat162* r;
    r = (__nv_bfloat162*)(g_znb + (size_t)p0 * DDIM);
    r[lane*2+0]    = __float22bfloat162_rn(make_float2(A0.x*ii0, A0.y*ii0));
    r[lane*2+1]    = __float22bfloat162_rn(make_float2(A0.z*ii0, A0.w*ii0));
    r[64+lane*2+0] = __float22bfloat162_rn(make_float2(A1.x*ii0, A1.y*ii0));
    r[64+lane*2+1] = __float22bfloat162_rn(make_float2(A1.z*ii0, A1.w*ii0));
    r = (__nv_bfloat162*)(g_znb + (size_t)(p0 + NHALF) * DDIM);
    r[lane*2+0]    = __float22bfloat162_rn(make_float2(B0.x*ij0, B0.y*ij0));
    r[lane*2+1]    = __float22bfloat162_rn(make_float2(B0.z*ij0, B0.w*ij0));
    r[64+lane*2+0] = __float22bfloat162_rn(make_float2(B1.x*ij0, B1.y*ij0));
    r[64+lane*2+1] = __float22bfloat162_rn(make_float2(B1.z*ij0, B1.w*ij0));
    r = (__nv_bfloat162*)(g_znb + (size_t)(p0 + 1) * DDIM);
    r[lane*2+0]    = __float22bfloat162_rn(make_float2(C0.x*ii1, C0.y*ii1));
    r[lane*2+1]    = __float22bfloat162_rn(make_float2(C0.z*ii1, C0.w*ii1));
    r[64+lane*2+0] = __float22bfloat162_rn(make_float2(C1.x*ii1, C1.y*ii1));
    r[64+lane*2+1] = __float22bfloat162_rn(make_float2(C1.z*ii1, C1.w*ii1));
    r = (__nv_bfloat162*)(g_znb + (size_t)(p0 + 1 + NHALF) * DDIM);
    r[lane*2+0]    = __float22bfloat162_rn(make_float2(D0.x*ij1, D0.y*ij1));
    r[lane*2+1]    = __float22bfloat162_rn(make_float2(D0.z*ij1, D0.w*ij1));
    r[64+lane*2+0] = __float22bfloat162_rn(make_float2(D1.x*ij1, D1.y*ij1));
    r[64+lane*2+1] = __float22bfloat162_rn(make_float2(D1.z*ij1, D1.w*ij1));
}

// ===================== Kernel 2: symmetric HMMA sim-GEMM + exp + sums =======
// Lower-triangle tiles only: 64*65/2 = 2080 CTAs (HW-scheduled).
// 128x128 per CTA; 16 warps (4x4), warp tile 32x32; K=256, 4 stages of BK=64.
// __launch_bounds__(512, 2): cap regs at 62 for 2 CTAs/SM = 32 warps/SM.
#define BM 128
#define BN 128
#define BK 64
#define NSTAGE 4
#define NTHR 512
#define NTB (NROWS / BM)
#define NTILES (NTB * (NTB + 1) / 2)

#define SMA      0
#define SMB      32768
#define SMROW    65536
#define SMCOL    66048
#define SM_TOTAL (66048 + 512)
#define STAGE_BYTES 16384

__global__ void __launch_bounds__(NTHR, 2) k_simexp() {
    extern __shared__ char smem[];
    float* srow = (float*)(smem + SMROW);
    float* scol = (float*)(smem + SMCOL);
    const uint32_t sb = smem_u32(smem);
    const int tid  = threadIdx.x;
    const int wid  = tid >> 5;
    const int lane = tid & 31;
    const int wr   = wid >> 2;     // warp row 0..3 (32 m-rows each)
    const int wc   = wid & 3;      // warp col 0..3 (32 n-cols each)

    // decode lower-triangle tile index: t = bi*(bi+1)/2 + bj, bj <= bi
    int t  = blockIdx.x;
    int bi = (int)((sqrtf(8.0f * (float)t + 1.0f) - 1.0f) * 0.5f);
    while ((bi + 1) * (bi + 2) / 2 <= t) ++bi;
    while (bi * (bi + 1) / 2 > t)        --bi;
    int bj = t - bi * (bi + 1) / 2;
    const int rb   = bi * BM;
    const int cb   = bj * BN;
    const bool diag = (bi == bj);

    if (tid < BM) { srow[tid] = 0.0f; scol[tid] = 0.0f; }

    const __nv_bfloat16* Agp = g_znb + (size_t)rb * DDIM;
    const __nv_bfloat16* Bgp = g_znb + (size_t)cb * DDIM;

    const uint32_t rowAb = (uint32_t)(wr * 32 + (lane & 15)) * 128u;
    const uint32_t rowBb = (uint32_t)(wc * 32 + (lane & 7) + ((lane >> 4) << 3)) * 128u;
    const uint32_t swzA0 = (uint32_t)(lane >> 4);
    const uint32_t swzB0 = (uint32_t)((lane >> 3) & 1);
    const uint32_t lxor  = (uint32_t)(lane & 7);

    float acc[2][4][4];
    #pragma unroll
    for (int mt = 0; mt < 2; ++mt)
        #pragma unroll
        for (int nt = 0; nt < 4; ++nt)
            #pragma unroll
            for (int e = 0; e < 4; ++e) acc[mt][nt][e] = 0.0f;

    auto load_stage = [&](int s, int buf) {
        const int k0 = s * BK;
        #pragma unroll
        for (int tt = 0; tt < 2; ++tt) {
            int idx = tid + tt * NTHR;     // 0..1023
            int r   = idx >> 3;            // 0..127
            int c   = idx & 7;
            uint32_t so = (uint32_t)r * 128u + (uint32_t)((c ^ (r & 7)) << 4);
            CP_ASYNC16(sb + SMA + buf * STAGE_BYTES + so, Agp + (size_t)r * DDIM + k0 + c * 8);
            if (!diag)
                CP_ASYNC16(sb + SMB + buf * STAGE_BYTES + so, Bgp + (size_t)r * DDIM + k0 + c * 8);
        }
        CP_COMMIT();
    };

    load_stage(0, 0);

    for (int s = 0; s < NSTAGE; ++s) {
        const int buf = s & 1;
        if (s + 1 < NSTAGE) { load_stage(s + 1, (s + 1) & 1); CP_WAIT_1(); }
        else                { CP_WAIT_0(); }
        __syncthreads();

        const uint32_t abase = sb + SMA + buf * STAGE_BYTES;
        const uint32_t bbase = diag ? abase : (sb + SMB + buf * STAGE_BYTES);

        #pragma unroll
        for (int ks = 0; ks < 4; ++ks) {
            uint32_t a[2][4];
            const uint32_t cA = (uint32_t)(ks * 2) + swzA0;
            const uint32_t aoff = abase + rowAb + ((cA ^ lxor) << 4);
            #pragma unroll
            for (int mt = 0; mt < 2; ++mt)
                LDSM_X4(a[mt][0], a[mt][1], a[mt][2], a[mt][3], aoff + mt * 2048);

            uint32_t b[2][4];
            const uint32_t cB = (uint32_t)(ks * 2) + swzB0;
            const uint32_t boff = bbase + rowBb + ((cB ^ lxor) << 4);
            #pragma unroll
            for (int bt = 0; bt < 2; ++bt)
                LDSM_X4(b[bt][0], b[bt][1], b[bt][2], b[bt][3], boff + bt * 2048);

            #pragma unroll
            for (int mt = 0; mt < 2; ++mt)
                #pragma unroll
                for (int nt = 0; nt < 4; ++nt)
                    MMA16816(acc[mt][nt], a[mt],
                             b[nt >> 1][(nt & 1) * 2], b[nt >> 1][(nt & 1) * 2 + 1]);
        }
        __syncthreads();
    }

    // ---- epilogue: exp(2*sim); rows always; cols when off-diagonal ---------
    // fragment: row = wr*32 + mt*16 + (lane>>2) (+8 for e2/e3)
    //           col = wc*32 + nt*8 + (lane&3)*2 (+1 for e1/e3)
    float csum0[4] = {0,0,0,0}, csum1[4] = {0,0,0,0};
    #pragma unroll
    for (int mt = 0; mt < 2; ++mt) {
        float slow = 0.0f, shigh = 0.0f;
        #pragma unroll
        for (int nt = 0; nt < 4; ++nt) {
            float e0 = ex2f(acc[mt][nt][0] * LOG2E_X2);
            float e1 = ex2f(acc[mt][nt][1] * LOG2E_X2);
            float e2 = ex2f(acc[mt][nt][2] * LOG2E_X2);
            float e3 = ex2f(acc[mt][nt][3] * LOG2E_X2);
            slow  += e0 + e1;
            shigh += e2 + e3;
            csum0[nt] += e0 + e2;
            csum1[nt] += e1 + e3;
        }
        #pragma unroll
        for (int o = 1; o < 4; o <<= 1) {
            slow  += __shfl_xor_sync(0xffffffffu, slow,  o);
            shigh += __shfl_xor_sync(0xffffffffu, shigh, o);
        }
        if ((lane & 3) == 0) {
            int r = wr * 32 + mt * 16 + (lane >> 2);
            atomicAdd(&srow[r],     slow);
            atomicAdd(&srow[r + 8], shigh);
        }
    }
    if (!diag) {
        #pragma unroll
        for (int nt = 0; nt < 4; ++nt) {
            #pragma unroll
            for (int o = 4; o < 32; o <<= 1) {
                csum0[nt] += __shfl_xor_sync(0xffffffffu, csum0[nt], o);
                csum1[nt] += __shfl_xor_sync(0xffffffffu, csum1[nt], o);
            }
            if (lane < 4) {
                int c = wc * 32 + nt * 8 + lane * 2;
                atomicAdd(&scol[c],     csum0[nt]);
                atomicAdd(&scol[c + 1], csum1[nt]);
            }
        }
    }
    __syncthreads();
    if (tid < BM) {
        atomicAdd(&g_rs[rb + tid], srow[tid]);
        if (!diag) atomicAdd(&g_rs[cb + tid], scol[tid]);
    }
}

// ===================== Kernel 3: S_d reduction + loss (32-block ticket) =====
#define SD_GRID 32
__global__ void __launch_bounds__(256) k_final(float* __restrict__ out) {
    __shared__ double red[256];
    __shared__ bool last;
    double s = 0.0;
    for (int r = blockIdx.x * 256 + threadIdx.x; r < NROWS; r += SD_GRID * 256) {
        float rs = g_rs[r];
        s += 8191.0 * (double)__logf(rs) + (double)__logf(fmaxf(rs - 1.0f, 1e-8f));
    }
    red[threadIdx.x] = s;
    __syncthreads();
    for (int o = 128; o > 0; o >>= 1) {
        if (threadIdx.x < o) red[threadIdx.x] += red[threadIdx.x + o];
        __syncthreads();
    }
    if (threadIdx.x == 0) {
        atomicAdd(&g_sd, red[0]);
        __threadfence();
        int old = atomicAdd(&g_ticket, 1);
        last = (old == SD_GRID - 1);
    }
    __syncthreads();
    if (last && threadIdx.x == 0) {
        double sd = atomicAdd(&g_sd, 0.0);   // atomic read (coherent)
        double loss = (sd - 8192.0 * (double)g_sum_p) / (8192.0 * 8192.0);
        out[0] = (float)loss;
    }
}

// ===================== launch ===============================================
extern "C" void kernel_launch(void* const* d_in, const int* in_sizes, int n_in,
                              void* d_out, int out_size) {
    (void)in_sizes; (void)n_in; (void)out_size;
    const float* zi = (const float*)d_in[0];
    const float* zj = (const float*)d_in[1];
    float* out = (float*)d_out;

    cudaFuncSetAttribute(k_simexp, cudaFuncAttributeMaxDynamicSharedMemorySize, SM_TOTAL);

    k_prep<<<256, 256>>>(zi, zj);
    k_simexp<<<NTILES, NTHR, SM_TOTAL>>>();
    k_final<<<SD_GRID, 256>>>(out);
}

// round 15
// speedup vs baseline: 1.3868x; 1.3868x over previous
#include <cuda_runtime.h>
#include <cuda_bf16.h>
#include <math.h>
#include <cstdint>

// NT-Xent loss, N=4096, D=256, T=0.5, EPS=1e-8.
// loss = (S_d - 2N*S_p) / (2N)^2
//   S_p = (2/T) * sum_i dot(z_i, z_j)/(|z_i||z_j|)   (fp32, from raw inputs)
//   S_d = sum_j [(2N-1)*log(rs_j) + log(max(rs_j-1,EPS))]
//   rs_j = sum_k exp(sim_jk/T); sim = zn@zn^T        (bf16 HMMA, symmetric:
//   lower-triangle tiles only; off-diag tiles emit row AND col sums)
// R15 = measured-optimal configuration (R10/R13, 69.7us). Experiment log:
//   fp8 mma.sync      103us (half-rate legacy path)   — rejected
//   persistent CTAs    90us (loses HW load balancing) — rejected
//   3-buffer pipeline  88us (racy + no gain)          — rejected
//   grid-wide ticket   88us (2080 same-addr atomics)  — rejected
//   512thr/62reg       97us (spills)                  — rejected

#define NROWS 8192
#define NHALF 4096
#define DDIM  256
#define LOG2E_X2 2.8853900817779268f   // exp(2s) = 2^(s*2*log2 e)

__device__ __nv_bfloat16 g_znb[NROWS * DDIM];   // bf16 normalized
__device__ float         g_rs [NROWS];
__device__ float         g_sum_p;
__device__ double        g_sd;
__device__ int           g_ticket;

// ===================== PTX helpers ==========================================
__device__ __forceinline__ uint32_t smem_u32(const void* p) {
    uint32_t a;
    asm("{ .reg .u64 t; cvta.to.shared.u64 t, %1; cvt.u32.u64 %0, t; }" : "=r"(a) : "l"(p));
    return a;
}
#define CP_ASYNC16(sm, gp) \
    asm volatile("cp.async.cg.shared.global [%0], [%1], 16;" :: "r"(sm), "l"(gp))
#define CP_COMMIT() asm volatile("cp.async.commit_group;" ::: "memory")
#define CP_WAIT_1() asm volatile("cp.async.wait_group 1;" ::: "memory")
#define CP_WAIT_0() asm volatile("cp.async.wait_group 0;" ::: "memory")

#define LDSM_X4(r0, r1, r2, r3, addr) \
    asm volatile("ldmatrix.sync.aligned.m8n8.x4.shared.b16 {%0,%1,%2,%3}, [%4];" \
        : "=r"(r0), "=r"(r1), "=r"(r2), "=r"(r3) : "r"(addr))

#define MMA16816(d, a, b0, b1) \
    asm volatile("mma.sync.aligned.m16n8k16.row.col.f32.bf16.bf16.f32 " \
        "{%0,%1,%2,%3}, {%4,%5,%6,%7}, {%8,%9}, {%0,%1,%2,%3};" \
        : "+f"((d)[0]), "+f"((d)[1]), "+f"((d)[2]), "+f"((d)[3]) \
        : "r"((a)[0]), "r"((a)[1]), "r"((a)[2]), "r"((a)[3]), "r"(b0), "r"(b1))

__device__ __forceinline__ float ex2f(float x) {
    float y; asm("ex2.approx.f32 %0, %1;" : "=f"(y) : "f"(x)); return y;
}

// ===================== Kernel 1: prep = normalize + positives ===============
// One warp per TWO pairs (MLP 8); writes bf16 zn rows; accumulates S_p.
__global__ void __launch_bounds__(256) k_prep(const float* __restrict__ zi,
                                              const float* __restrict__ zj) {
    int gtid = blockIdx.x * 256 + threadIdx.x;
    if (gtid < NROWS) g_rs[gtid] = 0.0f;
    if (gtid == 0) { g_sum_p = 0.0f; g_sd = 0.0; g_ticket = 0; }

    int warp = gtid >> 5;          // 0..2047
    int lane = threadIdx.x & 31;
    int p0   = warp * 2;
    if (p0 >= NHALF) return;

    const float4* a0p = (const float4*)(zi + (size_t)p0 * DDIM);
    const float4* b0p = (const float4*)(zj + (size_t)p0 * DDIM);
    const float4* a1p = (const float4*)(zi + (size_t)(p0 + 1) * DDIM);
    const float4* b1p = (const float4*)(zj + (size_t)(p0 + 1) * DDIM);
    float4 A0 = a0p[lane], A1 = a0p[lane + 32];
    float4 B0 = b0p[lane], B1 = b0p[lane + 32];
    float4 C0 = a1p[lane], C1 = a1p[lane + 32];
    float4 D0 = b1p[lane], D1 = b1p[lane + 32];

    float si0 = A0.x*A0.x+A0.y*A0.y+A0.z*A0.z+A0.w*A0.w + A1.x*A1.x+A1.y*A1.y+A1.z*A1.z+A1.w*A1.w;
    float sj0 = B0.x*B0.x+B0.y*B0.y+B0.z*B0.z+B0.w*B0.w + B1.x*B1.x+B1.y*B1.y+B1.z*B1.z+B1.w*B1.w;
    float dd0 = A0.x*B0.x+A0.y*B0.y+A0.z*B0.z+A0.w*B0.w + A1.x*B1.x+A1.y*B1.y+A1.z*B1.z+A1.w*B1.w;
    float si1 = C0.x*C0.x+C0.y*C0.y+C0.z*C0.z+C0.w*C0.w + C1.x*C1.x+C1.y*C1.y+C1.z*C1.z+C1.w*C1.w;
    float sj1 = D0.x*D0.x+D0.y*D0.y+D0.z*D0.z+D0.w*D0.w + D1.x*D1.x+D1.y*D1.y+D1.z*D1.z+D1.w*D1.w;
    float dd1 = C0.x*D0.x+C0.y*D0.y+C0.z*D0.z+C0.w*D0.w + C1.x*D1.x+C1.y*D1.y+C1.z*D1.z+C1.w*D1.w;
    #pragma unroll
    for (int o = 16; o > 0; o >>= 1) {
        si0 += __shfl_xor_sync(0xffffffffu, si0, o);
        sj0 += __shfl_xor_sync(0xffffffffu, sj0, o);
        dd0 += __shfl_xor_sync(0xffffffffu, dd0, o);
        si1 += __shfl_xor_sync(0xffffffffu, si1, o);
        sj1 += __shfl_xor_sync(0xffffffffu, sj1, o);
        dd1 += __shfl_xor_sync(0xffffffffu, dd1, o);
    }
    float ii0 = 1.0f / fmaxf(sqrtf(si0), 1e-8f);
    float ij0 = 1.0f / fmaxf(sqrtf(sj0), 1e-8f);
    float ii1 = 1.0f / fmaxf(sqrtf(si1), 1e-8f);
    float ij1 = 1.0f / fmaxf(sqrtf(sj1), 1e-8f);

    if (lane == 0)
        atomicAdd(&g_sum_p, 4.0f * (dd0 * ii0 * ij0 + dd1 * ii1 * ij1)); // 2/T = 4

    __nv_bfloat162* r;
    r = (__nv_bfloat162*)(g_znb + (size_t)p0 * DDIM);
    r[lane*2+0]    = __float22bfloat162_rn(make_float2(A0.x*ii0, A0.y*ii0));
    r[lane*2+1]    = __float22bfloat162_rn(make_float2(A0.z*ii0, A0.w*ii0));
    r[64+lane*2+0] = __float22bfloat162_rn(make_float2(A1.x*ii0, A1.y*ii0));
    r[64+lane*2+1] = __float22bfloat162_rn(make_float2(A1.z*ii0, A1.w*ii0));
    r = (__nv_bfloat162*)(g_znb + (size_t)(p0 + NHALF) * DDIM);
    r[lane*2+0]    = __float22bfloat162_rn(make_float2(B0.x*ij0, B0.y*ij0));
    r[lane*2+1]    = __float22bfloat162_rn(make_float2(B0.z*ij0, B0.w*ij0));
    r[64+lane*2+0] = __float22bfloat162_rn(make_float2(B1.x*ij0, B1.y*ij0));
    r[64+lane*2+1] = __float22bfloat162_rn(make_float2(B1.z*ij0, B1.w*ij0));
    r = (__nv_bfloat162*)(g_znb + (size_t)(p0 + 1) * DDIM);
    r[lane*2+0]    = __float22bfloat162_rn(make_float2(C0.x*ii1, C0.y*ii1));
    r[lane*2+1]    = __float22bfloat162_rn(make_float2(C0.z*ii1, C0.w*ii1));
    r[64+lane*2+0] = __float22bfloat162_rn(make_float2(C1.x*ii1, C1.y*ii1));
    r[64+lane*2+1] = __float22bfloat162_rn(make_float2(C1.z*ii1, C1.w*ii1));
    r = (__nv_bfloat162*)(g_znb + (size_t)(p0 + 1 + NHALF) * DDIM);
    r[lane*2+0]    = __float22bfloat162_rn(make_float2(D0.x*ij1, D0.y*ij1));
    r[lane*2+1]    = __float22bfloat162_rn(make_float2(D0.z*ij1, D0.w*ij1));
    r[64+lane*2+0] = __float22bfloat162_rn(make_float2(D1.x*ij1, D1.y*ij1));
    r[64+lane*2+1] = __float22bfloat162_rn(make_float2(D1.z*ij1, D1.w*ij1));
}

// ===================== Kernel 2: symmetric HMMA sim-GEMM + exp + sums =======
// Lower-triangle tiles only: 64*65/2 = 2080 CTAs (HW-scheduled; dynamic
// balancing beats persistence — measured R8 vs R9).
// 128x128 per CTA; 8 warps (2x4), warp tile 64x32; K=256, 4 stages of BK=64.
#define BM 128
#define BN 128
#define BK 64
#define NSTAGE 4
#define NTB (NROWS / BM)
#define NTILES (NTB * (NTB + 1) / 2)

#define SMA      0
#define SMB      32768
#define SMROW    65536
#define SMCOL    66048
#define SM_TOTAL (66048 + 512)
#define STAGE_BYTES 16384

__global__ void __launch_bounds__(256) k_simexp() {
    extern __shared__ char smem[];
    float* srow = (float*)(smem + SMROW);
    float* scol = (float*)(smem + SMCOL);
    const uint32_t sb = smem_u32(smem);
    const int tid  = threadIdx.x;
    const int wid  = tid >> 5;
    const int lane = tid & 31;
    const int wr   = wid >> 2;
    const int wc   = wid & 3;

    // decode lower-triangle tile index: t = bi*(bi+1)/2 + bj, bj <= bi
    int t  = blockIdx.x;
    int bi = (int)((sqrtf(8.0f * (float)t + 1.0f) - 1.0f) * 0.5f);
    while ((bi + 1) * (bi + 2) / 2 <= t) ++bi;
    while (bi * (bi + 1) / 2 > t)        --bi;
    int bj = t - bi * (bi + 1) / 2;
    const int rb   = bi * BM;
    const int cb   = bj * BN;
    const bool diag = (bi == bj);

    if (tid < BM) { srow[tid] = 0.0f; scol[tid] = 0.0f; }

    const __nv_bfloat16* Agp = g_znb + (size_t)rb * DDIM;
    const __nv_bfloat16* Bgp = g_znb + (size_t)cb * DDIM;

    const uint32_t rowAb = (uint32_t)(wr * 64 + (lane & 15)) * 128u;
    const uint32_t rowBb = (uint32_t)(wc * 32 + (lane & 7) + ((lane >> 4) << 3)) * 128u;
    const uint32_t swzA0 = (uint32_t)(lane >> 4);
    const uint32_t swzB0 = (uint32_t)((lane >> 3) & 1);
    const uint32_t lxor  = (uint32_t)(lane & 7);

    float acc[4][4][4];
    #pragma unroll
    for (int mt = 0; mt < 4; ++mt)
        #pragma unroll
        for (int nt = 0; nt < 4; ++nt)
            #pragma unroll
            for (int e = 0; e < 4; ++e) acc[mt][nt][e] = 0.0f;

    auto load_stage = [&](int s, int buf) {
        const int k0 = s * BK;
        #pragma unroll
        for (int tt = 0; tt < 4; ++tt) {
            int idx = tid + tt * 256;
            int r   = idx >> 3;
            int c   = idx & 7;
            uint32_t so = (uint32_t)r * 128u + (uint32_t)((c ^ (r & 7)) << 4);
            CP_ASYNC16(sb + SMA + buf * STAGE_BYTES + so, Agp + (size_t)r * DDIM + k0 + c * 8);
            if (!diag)
                CP_ASYNC16(sb + SMB + buf * STAGE_BYTES + so, Bgp + (size_t)r * DDIM + k0 + c * 8);
        }
        CP_COMMIT();
    };

    load_stage(0, 0);

    for (int s = 0; s < NSTAGE; ++s) {
        const int buf = s & 1;
        if (s + 1 < NSTAGE) { load_stage(s + 1, (s + 1) & 1); CP_WAIT_1(); }
        else                { CP_WAIT_0(); }
        __syncthreads();

        const uint32_t abase = sb + SMA + buf * STAGE_BYTES;
        const uint32_t bbase = diag ? abase : (sb + SMB + buf * STAGE_BYTES);

        #pragma unroll
        for (int ks = 0; ks < 4; ++ks) {
            uint32_t a[4][4];
            const uint32_t cA = (uint32_t)(ks * 2) + swzA0;
            const uint32_t aoff = abase + rowAb + ((cA ^ lxor) << 4);
            #pragma unroll
            for (int mt = 0; mt < 4; ++mt)
                LDSM_X4(a[mt][0], a[mt][1], a[mt][2], a[mt][3], aoff + mt * 2048);

            uint32_t b[2][4];
            const uint32_t cB = (uint32_t)(ks * 2) + swzB0;
            const uint32_t boff = bbase + rowBb + ((cB ^ lxor) << 4);
            #pragma unroll
            for (int bt = 0; bt < 2; ++bt)
                LDSM_X4(b[bt][0], b[bt][1], b[bt][2], b[bt][3], boff + bt * 2048);

            #pragma unroll
            for (int mt = 0; mt < 4; ++mt)
                #pragma unroll
                for (int nt = 0; nt < 4; ++nt)
                    MMA16816(acc[mt][nt], a[mt],
                             b[nt >> 1][(nt & 1) * 2], b[nt >> 1][(nt & 1) * 2 + 1]);
        }
        __syncthreads();
    }

    // ---- epilogue: exp(2*sim); rows always; cols when off-diagonal ---------
    float csum0[4] = {0,0,0,0}, csum1[4] = {0,0,0,0};
    #pragma unroll
    for (int mt = 0; mt < 4; ++mt) {
        float slow = 0.0f, shigh = 0.0f;
        #pragma unroll
        for (int nt = 0; nt < 4; ++nt) {
            float e0 = ex2f(acc[mt][nt][0] * LOG2E_X2);
            float e1 = ex2f(acc[mt][nt][1] * LOG2E_X2);
            float e2 = ex2f(acc[mt][nt][2] * LOG2E_X2);
            float e3 = ex2f(acc[mt][nt][3] * LOG2E_X2);
            slow  += e0 + e1;
            shigh += e2 + e3;
            csum0[nt] += e0 + e2;
            csum1[nt] += e1 + e3;
        }
        #pragma unroll
        for (int o = 1; o < 4; o <<= 1) {
            slow  += __shfl_xor_sync(0xffffffffu, slow,  o);
            shigh += __shfl_xor_sync(0xffffffffu, shigh, o);
        }
        if ((lane & 3) == 0) {
            int r = wr * 64 + mt * 16 + (lane >> 2);
            atomicAdd(&srow[r],     slow);
            atomicAdd(&srow[r + 8], shigh);
        }
    }
    if (!diag) {
        #pragma unroll
        for (int nt = 0; nt < 4; ++nt) {
            #pragma unroll
            for (int o = 4; o < 32; o <<= 1) {
                csum0[nt] += __shfl_xor_sync(0xffffffffu, csum0[nt], o);
                csum1[nt] += __shfl_xor_sync(0xffffffffu, csum1[nt], o);
            }
            if (lane < 4) {
                int c = wc * 32 + nt * 8 + lane * 2;
                atomicAdd(&scol[c],     csum0[nt]);
                atomicAdd(&scol[c + 1], csum1[nt]);
            }
        }
    }
    __syncthreads();
    if (tid < BM) {
        atomicAdd(&g_rs[rb + tid], srow[tid]);
        if (!diag) atomicAdd(&g_rs[cb + tid], scol[tid]);
    }
}

// ===================== Kernel 3: S_d reduction + loss (32-block ticket) =====
#define SD_GRID 32
__global__ void __launch_bounds__(256) k_final(float* __restrict__ out) {
    __shared__ double red[256];
    __shared__ bool last;
    double s = 0.0;
    for (int r = blockIdx.x * 256 + threadIdx.x; r < NROWS; r += SD_GRID * 256) {
        float rs = g_rs[r];
        s += 8191.0 * (double)__logf(rs) + (double)__logf(fmaxf(rs - 1.0f, 1e-8f));
    }
    red[threadIdx.x] = s;
    __syncthreads();
    for (int o = 128; o > 0; o >>= 1) {
        if (threadIdx.x < o) red[threadIdx.x] += red[threadIdx.x + o];
        __syncthreads();
    }
    if (threadIdx.x == 0) {
        atomicAdd(&g_sd, red[0]);
        __threadfence();
        int old = atomicAdd(&g_ticket, 1);
        last = (old == SD_GRID - 1);
    }
    __syncthreads();
    if (last && threadIdx.x == 0) {
        double sd = atomicAdd(&g_sd, 0.0);   // atomic read (coherent)
        double loss = (sd - 8192.0 * (double)g_sum_p) / (8192.0 * 8192.0);
        out[0] = (float)loss;
    }
}

// ===================== launch ===============================================
extern "C" void kernel_launch(void* const* d_in, const int* in_sizes, int n_in,
                              void* d_out, int out_size) {
    (void)in_sizes; (void)n_in; (void)out_size;
    const float* zi = (const float*)d_in[0];
    const float* zj = (const float*)d_in[1];
    float* out = (float*)d_out;

    cudaFuncSetAttribute(k_simexp, cudaFuncAttributeMaxDynamicSharedMemorySize, SM_TOTAL);

    k_prep<<<256, 256>>>(zi, zj);
    k_simexp<<<NTILES, 256, SM_TOTAL>>>();
    k_final<<<SD_GRID, 256>>>(out);
}